// round 1
// baseline (speedup 1.0000x reference)
#include <cuda_runtime.h>
#include <cuda_bf16.h>
#include <math.h>

// Problem constants
#define RR 64
#define SS 32
#define TT 50
#define EE 512
#define UU 20
#define DD 532
#define LL 9

// Scratch (device globals — no allocations allowed)
__device__ float g_sent_mean[RR * SS * EE];   // [2048, 512]
__device__ float g_sent_h[RR * SS * EE];      // [2048, 512]
__device__ float g_sent_mask[RR * SS];        // [2048]
__device__ float g_rev_mean[RR * EE];         // [64, 512]
__device__ float g_p_batch[RR * DD];          // [64, 532]

__device__ __forceinline__ float selu_f(float x) {
    const float scale = 1.0507009873554804934193349852946f;
    const float alpha = 1.6732632423543772848170429916717f;
    return x > 0.0f ? scale * x : scale * alpha * expm1f(x);
}

// ---------------------------------------------------------------------------
// K1: per-(r,s) masked mean over tokens (embedding gather)
// grid 2048, block 128, each thread owns 4 contiguous floats (float4)
// ---------------------------------------------------------------------------
__global__ void k1_sent_mean(const int* __restrict__ inputs,
                             const float* __restrict__ emb) {
    const int rs = blockIdx.x;
    const int tid = threadIdx.x;
    __shared__ int sidx[TT];
    if (tid < TT) sidx[tid] = inputs[rs * TT + tid];
    __syncthreads();

    float4 acc = make_float4(0.f, 0.f, 0.f, 0.f);
    int cnt = 0;
    #pragma unroll 2
    for (int t = 0; t < TT; t++) {
        const int ix = sidx[t];
        if (ix != 0) {
            cnt++;
            const float4 v = *reinterpret_cast<const float4*>(
                emb + (size_t)ix * EE + tid * 4);
            acc.x += v.x; acc.y += v.y; acc.z += v.z; acc.w += v.w;
        }
    }
    const float inv = 1.0f / (float)max(cnt, 1);
    acc.x *= inv; acc.y *= inv; acc.z *= inv; acc.w *= inv;
    *reinterpret_cast<float4*>(&g_sent_mean[(size_t)rs * EE + tid * 4]) = acc;
    if (tid == 0) g_sent_mask[rs] = (cnt > 0) ? 1.0f : 0.0f;
}

// ---------------------------------------------------------------------------
// Tiled fp32 GEMM: C[M,N](ldc) = selu(A[M,K] @ B[K,N] + bias)
// BM=BN=64, BK=16, 256 threads, 4x4 micro-tile
// ---------------------------------------------------------------------------
__device__ __forceinline__ void gemm_bias_selu_body(
    const float* __restrict__ A, const float* __restrict__ B,
    const float* __restrict__ bias, float* __restrict__ C,
    int M, int N, int K, int ldc)
{
    __shared__ float As[16][64];
    __shared__ float Bs[16][64];
    const int t = threadIdx.x;
    const int m0 = blockIdx.y * 64;
    const int n0 = blockIdx.x * 64;
    const int mb = (t / 16) * 4;
    const int nb = (t % 16) * 4;

    const int a_row = t / 4;          // 0..63
    const int a_col = (t % 4) * 4;    // 0,4,8,12
    const int b_row = t / 16;         // 0..15
    const int b_col = (t % 16) * 4;   // 0..60

    float acc[4][4] = {};

    for (int k0 = 0; k0 < K; k0 += 16) {
        const float4 av = *reinterpret_cast<const float4*>(
            &A[(size_t)(m0 + a_row) * K + k0 + a_col]);
        As[a_col + 0][a_row] = av.x;
        As[a_col + 1][a_row] = av.y;
        As[a_col + 2][a_row] = av.z;
        As[a_col + 3][a_row] = av.w;
        *reinterpret_cast<float4*>(&Bs[b_row][b_col]) =
            *reinterpret_cast<const float4*>(
                &B[(size_t)(k0 + b_row) * N + n0 + b_col]);
        __syncthreads();
        #pragma unroll
        for (int kk = 0; kk < 16; kk++) {
            const float4 a = *reinterpret_cast<const float4*>(&As[kk][mb]);
            const float4 b = *reinterpret_cast<const float4*>(&Bs[kk][nb]);
            acc[0][0] += a.x * b.x; acc[0][1] += a.x * b.y;
            acc[0][2] += a.x * b.z; acc[0][3] += a.x * b.w;
            acc[1][0] += a.y * b.x; acc[1][1] += a.y * b.y;
            acc[1][2] += a.y * b.z; acc[1][3] += a.y * b.w;
            acc[2][0] += a.z * b.x; acc[2][1] += a.z * b.y;
            acc[2][2] += a.z * b.z; acc[2][3] += a.z * b.w;
            acc[3][0] += a.w * b.x; acc[3][1] += a.w * b.y;
            acc[3][2] += a.w * b.z; acc[3][3] += a.w * b.w;
        }
        __syncthreads();
    }

    const float4 bi = *reinterpret_cast<const float4*>(&bias[n0 + nb]);
    #pragma unroll
    for (int i = 0; i < 4; i++) {
        float4 o;
        o.x = selu_f(acc[i][0] + bi.x);
        o.y = selu_f(acc[i][1] + bi.y);
        o.z = selu_f(acc[i][2] + bi.z);
        o.w = selu_f(acc[i][3] + bi.w);
        *reinterpret_cast<float4*>(&C[(size_t)(m0 + mb + i) * ldc + n0 + nb]) = o;
    }
}

__global__ void k2_sent_gemm(const float* __restrict__ W,
                             const float* __restrict__ bias) {
    gemm_bias_selu_body(g_sent_mean, W, bias, g_sent_h,
                        RR * SS, EE, EE, EE);
}

__global__ void k4_rev_gemm(const float* __restrict__ W,
                            const float* __restrict__ bias) {
    gemm_bias_selu_body(g_rev_mean, W, bias, g_p_batch,
                        RR, EE, EE, DD);
}

// ---------------------------------------------------------------------------
// K3: masked mean over sentences -> rev_mean [64,512]
// ---------------------------------------------------------------------------
__global__ void k3_rev_mean() {
    const int r = blockIdx.x;
    const int tid = threadIdx.x;
    float4 acc = make_float4(0.f, 0.f, 0.f, 0.f);
    float cnt = 0.f;
    #pragma unroll 4
    for (int s = 0; s < SS; s++) {
        const float m = g_sent_mask[r * SS + s];
        if (m != 0.f) {
            cnt += 1.f;
            const float4 v = *reinterpret_cast<const float4*>(
                &g_sent_h[(size_t)(r * SS + s) * EE + tid * 4]);
            acc.x += v.x; acc.y += v.y; acc.z += v.z; acc.w += v.w;
        }
    }
    const float inv = 1.0f / fmaxf(cnt, 1.0f);
    acc.x *= inv; acc.y *= inv; acc.z *= inv; acc.w *= inv;
    *reinterpret_cast<float4*>(&g_rev_mean[(size_t)r * EE + tid * 4]) = acc;
}

// ---------------------------------------------------------------------------
// K_uf: L2-normalize user feats, scale by user_w, write p_batch cols [512,532)
// grid 64, block 32
// ---------------------------------------------------------------------------
__global__ void k_uf(const float* __restrict__ user_feats,
                     const float* __restrict__ user_w) {
    const int r = blockIdx.x;
    const int lane = threadIdx.x;
    const float v = (lane < UU) ? user_feats[r * UU + lane] : 0.f;
    float s = v * v;
    #pragma unroll
    for (int o = 16; o > 0; o >>= 1) s += __shfl_xor_sync(0xffffffff, s, o);
    const float denom = fmaxf(sqrtf(s), 1e-12f);
    if (lane < UU)
        g_p_batch[r * DD + EE + lane] = v / denom * user_w[lane];
}

// ---------------------------------------------------------------------------
// K_rstars: r_stars[r] = selu(dot(p_batch[r], w_rff) + b_rff) -> out[9+r]
// grid 64, block 128
// ---------------------------------------------------------------------------
__global__ void k_rstars(const float* __restrict__ w_rff,
                         const float* __restrict__ b_rff,
                         float* __restrict__ out) {
    const int r = blockIdx.x;
    const int tid = threadIdx.x;
    float acc = 0.f;
    for (int j = tid; j < DD; j += 128)
        acc += g_p_batch[r * DD + j] * w_rff[j];
    __shared__ float red[128];
    red[tid] = acc;
    __syncthreads();
    if (tid < 64) red[tid] += red[tid + 64];
    __syncthreads();
    if (tid < 32) {
        float v = red[tid] + red[tid + 32];
        #pragma unroll
        for (int o = 16; o > 0; o >>= 1) v += __shfl_xor_sync(0xffffffff, v, o);
        if (tid == 0) out[LL + r] = selu_f(v + b_rff[0]);
    }
}

// ---------------------------------------------------------------------------
// K_final: p_mean -> h_n -> p_stars. Single block of 544 threads.
// ---------------------------------------------------------------------------
__global__ void k_final(const float* __restrict__ w_prod,
                        const float* __restrict__ b_prod,
                        const float* __restrict__ w_pff,
                        const float* __restrict__ b_pff,
                        float* __restrict__ out) {
    const int tid = threadIdx.x;
    __shared__ float pm[DD];
    __shared__ float hn[DD];
    __shared__ float wp[DD * LL];

    for (int i = tid; i < DD * LL; i += blockDim.x) wp[i] = w_pff[i];

    if (tid < DD) {
        float s = 0.f;
        #pragma unroll 4
        for (int r = 0; r < RR; r++) s += g_p_batch[r * DD + tid];
        pm[tid] = s * (1.0f / RR);
    }
    __syncthreads();

    if (tid < DD) {
        float acc = b_prod[tid];
        for (int k = 0; k < DD; k++)
            acc += pm[k] * w_prod[(size_t)k * DD + tid];
        hn[tid] = selu_f(acc);
    }
    __syncthreads();

    if (tid < LL) {
        float acc = b_pff[tid];
        for (int k = 0; k < DD; k++)
            acc += hn[k] * wp[k * LL + tid];
        out[tid] = selu_f(acc);
    }
}

// ---------------------------------------------------------------------------
extern "C" void kernel_launch(void* const* d_in, const int* in_sizes, int n_in,
                              void* d_out, int out_size) {
    const int*   inputs     = (const int*)  d_in[0];
    const float* user_feats = (const float*)d_in[1];
    const float* embedding  = (const float*)d_in[2];
    const float* w_sent     = (const float*)d_in[3];
    const float* b_sent     = (const float*)d_in[4];
    const float* w_rev      = (const float*)d_in[5];
    const float* b_rev      = (const float*)d_in[6];
    const float* w_prod     = (const float*)d_in[7];
    const float* b_prod     = (const float*)d_in[8];
    const float* w_rff      = (const float*)d_in[9];
    const float* b_rff      = (const float*)d_in[10];
    const float* w_pff      = (const float*)d_in[11];
    const float* b_pff      = (const float*)d_in[12];
    const float* user_w     = (const float*)d_in[13];
    float* out = (float*)d_out;

    k1_sent_mean<<<RR * SS, 128>>>(inputs, embedding);
    k_uf<<<RR, 32>>>(user_feats, user_w);
    k2_sent_gemm<<<dim3(EE / 64, (RR * SS) / 64), 256>>>(w_sent, b_sent);
    k3_rev_mean<<<RR, 128>>>();
    k4_rev_gemm<<<dim3(EE / 64, 1), 256>>>(w_rev, b_rev);
    k_rstars<<<RR, 128>>>(w_rff, b_rff, out);
    k_final<<<1, 544>>>(w_prod, b_prod, w_pff, b_pff, out);
}

// round 2
// speedup vs baseline: 1.3302x; 1.3302x over previous
#include <cuda_runtime.h>
#include <cuda_bf16.h>
#include <math.h>

#define RR 64
#define SS 32
#define TT 50
#define EE 512
#define UU 20
#define DD 532
#define LL 9
#define KZ4 8          // split-K factor for rev GEMM

// Scratch (device globals — no allocations allowed)
__device__ float g_sent_mean[RR * SS * EE];      // [2048, 512]
__device__ float g_sent_h[RR * SS * EE];         // [2048, 512]
__device__ float g_sent_mask[RR * SS];           // [2048]
__device__ float g_rev_mean[RR * EE];            // [64, 512]
__device__ float g_p_batch[RR * DD];             // [64, 532]
__device__ float g_k4part[KZ4 * RR * EE];        // [8, 64, 512]
__device__ float g_pm[DD];
__device__ float g_hn[DD];

__device__ __forceinline__ float selu_f(float x) {
    const float scale = 1.0507009873554804934193349852946f;
    const float alpha = 1.6732632423543772848170429916717f;
    return x > 0.0f ? scale * x : scale * alpha * expm1f(x);
}

// ---------------------------------------------------------------------------
// K1: per-(r,s) masked mean over tokens (embedding gather)
// grid 2048, block 128
// ---------------------------------------------------------------------------
__global__ void k1_sent_mean(const int* __restrict__ inputs,
                             const float* __restrict__ emb) {
    const int rs = blockIdx.x;
    const int tid = threadIdx.x;
    __shared__ int sidx[TT];
    if (tid < TT) sidx[tid] = inputs[rs * TT + tid];
    __syncthreads();

    float4 acc = make_float4(0.f, 0.f, 0.f, 0.f);
    int cnt = 0;
    #pragma unroll 2
    for (int t = 0; t < TT; t++) {
        const int ix = sidx[t];
        if (ix != 0) {
            cnt++;
            const float4 v = *reinterpret_cast<const float4*>(
                emb + (size_t)ix * EE + tid * 4);
            acc.x += v.x; acc.y += v.y; acc.z += v.z; acc.w += v.w;
        }
    }
    const float inv = 1.0f / (float)max(cnt, 1);
    acc.x *= inv; acc.y *= inv; acc.z *= inv; acc.w *= inv;
    *reinterpret_cast<float4*>(&g_sent_mean[(size_t)rs * EE + tid * 4]) = acc;
    if (tid == 0) g_sent_mask[rs] = (cnt > 0) ? 1.0f : 0.0f;
}

// ---------------------------------------------------------------------------
// K2: sentence GEMM. C[2048,512] = selu(A @ W + b)
// BM=128, BN=64, BK=16, 256 threads, 8x4 microtile, reg-prefetch dbl buffer
// grid (512/64, 2048/128) = (8, 16) = 128 blocks
// ---------------------------------------------------------------------------
__global__ __launch_bounds__(256) void k2_sent_gemm(
    const float* __restrict__ W, const float* __restrict__ bias)
{
    __shared__ float As[16][128];
    __shared__ float Bs[16][64];
    const int t = threadIdx.x;
    const int m0 = blockIdx.y * 128;
    const int n0 = blockIdx.x * 64;
    const int tm = (t >> 4) << 3;   // 8-row group
    const int tn = (t & 15) << 2;   // 4-col group

    // A-load mapping: 2 float4 per thread
    const int f0 = t * 2, f1 = t * 2 + 1;
    const int ar0 = f0 >> 2, ac0 = (f0 & 3) << 2;
    const int ar1 = f1 >> 2, ac1 = (f1 & 3) << 2;
    // B-load mapping: 1 float4 per thread
    const int br = t >> 4, bc = (t & 15) << 2;

    const float* A = g_sent_mean;

    float4 a_reg0, a_reg1, b_reg;
    a_reg0 = *(const float4*)&A[(size_t)(m0 + ar0) * EE + ac0];
    a_reg1 = *(const float4*)&A[(size_t)(m0 + ar1) * EE + ac1];
    b_reg  = *(const float4*)&W[(size_t)br * EE + n0 + bc];

    float acc[8][4] = {};

    for (int k0 = 0; k0 < EE; k0 += 16) {
        As[ac0 + 0][ar0] = a_reg0.x; As[ac0 + 1][ar0] = a_reg0.y;
        As[ac0 + 2][ar0] = a_reg0.z; As[ac0 + 3][ar0] = a_reg0.w;
        As[ac1 + 0][ar1] = a_reg1.x; As[ac1 + 1][ar1] = a_reg1.y;
        As[ac1 + 2][ar1] = a_reg1.z; As[ac1 + 3][ar1] = a_reg1.w;
        *(float4*)&Bs[br][bc] = b_reg;
        __syncthreads();

        if (k0 + 16 < EE) {
            const int kn = k0 + 16;
            a_reg0 = *(const float4*)&A[(size_t)(m0 + ar0) * EE + kn + ac0];
            a_reg1 = *(const float4*)&A[(size_t)(m0 + ar1) * EE + kn + ac1];
            b_reg  = *(const float4*)&W[(size_t)(kn + br) * EE + n0 + bc];
        }

        #pragma unroll
        for (int kk = 0; kk < 16; kk++) {
            const float4 a0 = *(const float4*)&As[kk][tm];
            const float4 a1 = *(const float4*)&As[kk][tm + 4];
            const float4 b  = *(const float4*)&Bs[kk][tn];
            const float am[8] = {a0.x, a0.y, a0.z, a0.w, a1.x, a1.y, a1.z, a1.w};
            #pragma unroll
            for (int i = 0; i < 8; i++) {
                acc[i][0] += am[i] * b.x;
                acc[i][1] += am[i] * b.y;
                acc[i][2] += am[i] * b.z;
                acc[i][3] += am[i] * b.w;
            }
        }
        __syncthreads();
    }

    const float4 bi = *(const float4*)&bias[n0 + tn];
    #pragma unroll
    for (int i = 0; i < 8; i++) {
        float4 o;
        o.x = selu_f(acc[i][0] + bi.x);
        o.y = selu_f(acc[i][1] + bi.y);
        o.z = selu_f(acc[i][2] + bi.z);
        o.w = selu_f(acc[i][3] + bi.w);
        *(float4*)&g_sent_h[(size_t)(m0 + tm + i) * EE + n0 + tn] = o;
    }
}

// ---------------------------------------------------------------------------
// K3: masked mean over sentences -> rev_mean [64,512]
// grid (4, 64), block 128: one scalar column per thread
// ---------------------------------------------------------------------------
__global__ void k3_rev_mean() {
    const int r = blockIdx.y;
    const int col = blockIdx.x * 128 + threadIdx.x;
    float acc = 0.f;
    float cnt = 0.f;
    #pragma unroll 8
    for (int s = 0; s < SS; s++) {
        const float m = g_sent_mask[r * SS + s];
        cnt += m;
        acc += m * g_sent_h[(size_t)(r * SS + s) * EE + col];
    }
    g_rev_mean[(size_t)r * EE + col] = acc / fmaxf(cnt, 1.0f);
}

// ---------------------------------------------------------------------------
// K4: review GEMM split-K. partial[kz] += rev_mean[:, kz*64:+64] @ W[kz*64:+64, :]
// BM=64, BN=64, BK=16, 256 threads, 4x4 microtile
// grid (8 n-tiles, 8 kz) = 64 blocks
// ---------------------------------------------------------------------------
__global__ __launch_bounds__(256) void k4_rev_gemm(const float* __restrict__ W) {
    __shared__ float As[16][64];
    __shared__ float Bs[16][64];
    const int t = threadIdx.x;
    const int n0 = blockIdx.x * 64;
    const int kz = blockIdx.y;
    const int kb = kz * 64;
    const int tm = (t >> 4) << 2;
    const int tn = (t & 15) << 2;

    const int ar = t >> 2, ac = (t & 3) << 2;   // A: 1 float4/thread
    const int br = t >> 4, bc = (t & 15) << 2;  // B: 1 float4/thread

    float4 a_reg = *(const float4*)&g_rev_mean[(size_t)ar * EE + kb + ac];
    float4 b_reg = *(const float4*)&W[(size_t)(kb + br) * EE + n0 + bc];

    float acc[4][4] = {};
    for (int k0 = 0; k0 < 64; k0 += 16) {
        As[ac + 0][ar] = a_reg.x; As[ac + 1][ar] = a_reg.y;
        As[ac + 2][ar] = a_reg.z; As[ac + 3][ar] = a_reg.w;
        *(float4*)&Bs[br][bc] = b_reg;
        __syncthreads();
        if (k0 + 16 < 64) {
            a_reg = *(const float4*)&g_rev_mean[(size_t)ar * EE + kb + k0 + 16 + ac];
            b_reg = *(const float4*)&W[(size_t)(kb + k0 + 16 + br) * EE + n0 + bc];
        }
        #pragma unroll
        for (int kk = 0; kk < 16; kk++) {
            const float4 a = *(const float4*)&As[kk][tm];
            const float4 b = *(const float4*)&Bs[kk][tn];
            const float am[4] = {a.x, a.y, a.z, a.w};
            #pragma unroll
            for (int i = 0; i < 4; i++) {
                acc[i][0] += am[i] * b.x;
                acc[i][1] += am[i] * b.y;
                acc[i][2] += am[i] * b.z;
                acc[i][3] += am[i] * b.w;
            }
        }
        __syncthreads();
    }
    float* P = g_k4part + (size_t)kz * RR * EE;
    #pragma unroll
    for (int i = 0; i < 4; i++) {
        *(float4*)&P[(size_t)(tm + i) * EE + n0 + tn] =
            make_float4(acc[i][0], acc[i][1], acc[i][2], acc[i][3]);
    }
}

// ---------------------------------------------------------------------------
// K_uf: L2-normalize user feats, scale by user_w -> p_batch cols [512,532)
// ---------------------------------------------------------------------------
__global__ void k_uf(const float* __restrict__ user_feats,
                     const float* __restrict__ user_w) {
    const int r = blockIdx.x;
    const int lane = threadIdx.x;
    const float v = (lane < UU) ? user_feats[r * UU + lane] : 0.f;
    float s = v * v;
    #pragma unroll
    for (int o = 16; o > 0; o >>= 1) s += __shfl_xor_sync(0xffffffff, s, o);
    const float denom = fmaxf(sqrtf(s), 1e-12f);
    if (lane < UU)
        g_p_batch[r * DD + EE + lane] = v / denom * user_w[lane];
}

// ---------------------------------------------------------------------------
// K5: reduce split-K partials + bias + selu -> p_batch[:, :512];
//     fused per-review star head -> out[9 + r]
// grid 64, block 128 (each thread owns a float4 column group)
// ---------------------------------------------------------------------------
__global__ void k5_reduce_rstars(const float* __restrict__ b_rev,
                                 const float* __restrict__ w_rff,
                                 const float* __restrict__ b_rff,
                                 float* __restrict__ out) {
    const int r = blockIdx.x;
    const int tid = threadIdx.x;
    const int col = tid * 4;

    float4 acc = *(const float4*)&b_rev[col];
    #pragma unroll
    for (int kz = 0; kz < KZ4; kz++) {
        const float4 p = *(const float4*)
            &g_k4part[(size_t)kz * RR * EE + (size_t)r * EE + col];
        acc.x += p.x; acc.y += p.y; acc.z += p.z; acc.w += p.w;
    }
    acc.x = selu_f(acc.x); acc.y = selu_f(acc.y);
    acc.z = selu_f(acc.z); acc.w = selu_f(acc.w);
    *(float4*)&g_p_batch[(size_t)r * DD + col] = acc;

    // r_stars dot product over all 532 cols
    const float4 w = *(const float4*)&w_rff[col];
    float local = acc.x * w.x + acc.y * w.y + acc.z * w.z + acc.w * w.w;
    if (tid < UU)
        local += g_p_batch[(size_t)r * DD + EE + tid] * w_rff[EE + tid];

    __shared__ float red[128];
    red[tid] = local;
    __syncthreads();
    if (tid < 64) red[tid] += red[tid + 64];
    __syncthreads();
    if (tid < 32) {
        float v = red[tid] + red[tid + 32];
        #pragma unroll
        for (int o = 16; o > 0; o >>= 1) v += __shfl_xor_sync(0xffffffff, v, o);
        if (tid == 0) out[LL + r] = selu_f(v + b_rff[0]);
    }
}

// ---------------------------------------------------------------------------
// KF1: pm = mean over reviews of p_batch  (grid 5, block 128)
// ---------------------------------------------------------------------------
__global__ void kf1_pmean() {
    const int c = blockIdx.x * 128 + threadIdx.x;
    if (c >= DD) return;
    float s = 0.f;
    #pragma unroll 8
    for (int r = 0; r < RR; r++) s += g_p_batch[(size_t)r * DD + c];
    g_pm[c] = s * (1.0f / RR);
}

// ---------------------------------------------------------------------------
// KF2: h_n = selu(pm @ w_prod + b_prod)   (grid 5, block 128)
// ---------------------------------------------------------------------------
__global__ void kf2_hn(const float* __restrict__ w_prod,
                       const float* __restrict__ b_prod) {
    __shared__ float pm_s[DD];
    for (int i = threadIdx.x; i < DD; i += 128) pm_s[i] = g_pm[i];
    __syncthreads();
    const int n = blockIdx.x * 128 + threadIdx.x;
    if (n >= DD) return;
    float acc = b_prod[n];
    for (int k = 0; k < DD; k++)
        acc += pm_s[k] * w_prod[(size_t)k * DD + n];
    g_hn[n] = selu_f(acc);
}

// ---------------------------------------------------------------------------
// KF3: p_stars = selu(h_n @ w_pff + b_pff)   (1 block, 9 warps)
// ---------------------------------------------------------------------------
__global__ void kf3_pstars(const float* __restrict__ w_pff,
                           const float* __restrict__ b_pff,
                           float* __restrict__ out) {
    const int w = threadIdx.x / 32;   // 0..8 -> label
    const int lane = threadIdx.x % 32;
    float acc = 0.f;
    for (int k = lane; k < DD; k += 32)
        acc += g_hn[k] * w_pff[k * LL + w];
    #pragma unroll
    for (int o = 16; o > 0; o >>= 1) acc += __shfl_xor_sync(0xffffffff, acc, o);
    if (lane == 0) out[w] = selu_f(acc + b_pff[w]);
}

// ---------------------------------------------------------------------------
extern "C" void kernel_launch(void* const* d_in, const int* in_sizes, int n_in,
                              void* d_out, int out_size) {
    const int*   inputs     = (const int*)  d_in[0];
    const float* user_feats = (const float*)d_in[1];
    const float* embedding  = (const float*)d_in[2];
    const float* w_sent     = (const float*)d_in[3];
    const float* b_sent     = (const float*)d_in[4];
    const float* w_rev      = (const float*)d_in[5];
    const float* b_rev      = (const float*)d_in[6];
    const float* w_prod     = (const float*)d_in[7];
    const float* b_prod     = (const float*)d_in[8];
    const float* w_rff      = (const float*)d_in[9];
    const float* b_rff      = (const float*)d_in[10];
    const float* w_pff      = (const float*)d_in[11];
    const float* b_pff      = (const float*)d_in[12];
    const float* user_w     = (const float*)d_in[13];
    float* out = (float*)d_out;

    k1_sent_mean<<<RR * SS, 128>>>(inputs, embedding);
    k_uf<<<RR, 32>>>(user_feats, user_w);
    k2_sent_gemm<<<dim3(EE / 64, (RR * SS) / 128), 256>>>(w_sent, b_sent);
    k3_rev_mean<<<dim3(4, RR), 128>>>();
    k4_rev_gemm<<<dim3(EE / 64, KZ4), 256>>>(w_rev);
    k5_reduce_rstars<<<RR, 128>>>(b_rev, w_rff, b_rff, out);
    kf1_pmean<<<5, 128>>>();
    kf2_hn<<<5, 128>>>(w_prod, b_prod);
    kf3_pstars<<<1, 288>>>(w_pff, b_pff, out);
}